// round 6
// baseline (speedup 1.0000x reference)
#include <cuda_runtime.h>
#include <cuda_fp16.h>
#include <cstdint>

// Problem constants
#define kR 8
#define kH 8
#define kDK 16
#define kD 128   // IN_DIM == OUT_DIM

// ---------------- scratch layout (single __device__ pool, float units) ----
#define OFF_Q     0ull
#define OFF_K     6400000ull
#define OFF_V     12800000ull
#define OFF_T     19200000ull
#define OFF_KRELH 25600000ull
#define OFF_VRELH 51200000ull
#define OFF_CNT   76800000ull
#define OFF_CUR   77300000ull
#define OFF_BSUM  77800000ull
#define OFF_SSRC  77810000ull
#define POOL_SZ   79500000ull

__device__ float g_pool[POOL_SZ];

// ---------------- SIMT sgemm: C[n,128] = A[n,128] @ W[128,128]^T + bias ----
// fuse==1: C = alpha*(AB^T+bias) + (1-alpha)*S,  alpha = sigmoid(skip[0])
__global__ __launch_bounds__(256) void gemm_out128(
    const float* __restrict__ A, const float* __restrict__ W,
    const float* __restrict__ bias, const float* __restrict__ S,
    const float* __restrict__ skipv, float* __restrict__ C,
    int n, int fuse)
{
    __shared__ float As[8][128];
    __shared__ float Bs[8][128];
    int row0 = blockIdx.x * 128;
    int tid = threadIdx.x;
    int tr = (tid >> 4) << 3;
    int tc = (tid & 15) << 3;
    float acc[8][8];
#pragma unroll
    for (int i = 0; i < 8; i++)
#pragma unroll
        for (int j = 0; j < 8; j++) acc[i][j] = 0.f;

    int li = tid >> 1;
    int lk = (tid & 1) << 2;
    for (int k0 = 0; k0 < 128; k0 += 8) {
        float4 a4 = make_float4(0.f, 0.f, 0.f, 0.f);
        if (row0 + li < n)
            a4 = *(const float4*)(A + (size_t)(row0 + li) * 128 + k0 + lk);
        As[lk + 0][li] = a4.x; As[lk + 1][li] = a4.y;
        As[lk + 2][li] = a4.z; As[lk + 3][li] = a4.w;
        float4 b4 = *(const float4*)(W + (size_t)li * 128 + k0 + lk);
        Bs[lk + 0][li] = b4.x; Bs[lk + 1][li] = b4.y;
        Bs[lk + 2][li] = b4.z; Bs[lk + 3][li] = b4.w;
        __syncthreads();
#pragma unroll
        for (int kk = 0; kk < 8; kk++) {
            float ar[8], br[8];
#pragma unroll
            for (int i = 0; i < 8; i++) ar[i] = As[kk][tr + i];
#pragma unroll
            for (int j = 0; j < 8; j++) br[j] = Bs[kk][tc + j];
#pragma unroll
            for (int i = 0; i < 8; i++)
#pragma unroll
                for (int j = 0; j < 8; j++) acc[i][j] += ar[i] * br[j];
        }
        __syncthreads();
    }
    float alpha = 1.f, beta = 0.f;
    if (fuse) {
        float sv = skipv[0];
        alpha = 1.f / (1.f + expf(-sv));
        beta = 1.f - alpha;
    }
#pragma unroll
    for (int i = 0; i < 8; i++) {
        int r = row0 + tr + i;
        if (r >= n) break;
#pragma unroll
        for (int j = 0; j < 8; j++) {
            int c = tc + j;
            float val = acc[i][j] + bias[c];
            if (fuse) val = alpha * val + beta * S[(size_t)r * 128 + c];
            C[(size_t)r * 128 + c] = val;
        }
    }
}

// ---------------- relation transforms -> fp16 krel/vrel [R,N,128] ---------
#define RT_TILE 32
__global__ __launch_bounds__(256) void rel_transform_h(
    const float* __restrict__ k, const float* __restrict__ v,
    const float* __restrict__ ratt, const float* __restrict__ rmsg,
    __half2* __restrict__ krel, __half2* __restrict__ vrel, int n)
{
    __shared__ float ks[RT_TILE][128];
    __shared__ float vs[RT_TILE][128];
    __shared__ float ma[2048];
    __shared__ float mm[2048];
    int node0 = blockIdx.x * RT_TILE;
    int tid = threadIdx.x;
    for (int i = tid; i < RT_TILE * 32; i += 256) {
        int nd = i >> 5, c4 = i & 31;
        if (node0 + nd < n) {
            ((float4*)ks[nd])[c4] = ((const float4*)(k + (size_t)(node0 + nd) * 128))[c4];
            ((float4*)vs[nd])[c4] = ((const float4*)(v + (size_t)(node0 + nd) * 128))[c4];
        }
    }
    int cp = tid & 63;      // half2 column index 0..63
    int c0 = cp << 1;       // even component
    int h = c0 >> 4;
    int e0 = c0 & 15;
    int nsub = tid >> 6;    // 0..3
    for (int r = 0; r < kR; r++) {
        __syncthreads();
        for (int i = tid; i < 2048; i += 256) {
            ma[i] = ratt[r * 2048 + i];
            mm[i] = rmsg[r * 2048 + i];
        }
        __syncthreads();
        for (int nd = nsub; nd < RT_TILE; nd += 4) {
            int gn = node0 + nd;
            if (gn >= n) break;
            float a0 = 0.f, a1 = 0.f, m0 = 0.f, m1 = 0.f;
#pragma unroll
            for (int d = 0; d < 16; d++) {
                float kk = ks[nd][h * 16 + d];
                float vv = vs[nd][h * 16 + d];
                int mi = (h * 16 + d) * 16 + e0;
                a0 += kk * ma[mi];     a1 += kk * ma[mi + 1];
                m0 += vv * mm[mi];     m1 += vv * mm[mi + 1];
            }
            size_t ob = ((size_t)r * n + gn) * 64 + cp;
            krel[ob] = __floats2half2_rn(a0, a1);
            vrel[ob] = __floats2half2_rn(m0, m1);
        }
    }
}

// ---------------- counting sort by seg = dst*8 + etype --------------------
__global__ void zero_cnt(unsigned* __restrict__ cnt, int nseg) {
    int i = blockIdx.x * blockDim.x + threadIdx.x;
    if (i <= nseg) cnt[i] = 0u;
}

__global__ void hist_kernel(const int* __restrict__ dst, const int* __restrict__ et,
                            unsigned* __restrict__ cnt, int e) {
    int i = blockIdx.x * blockDim.x + threadIdx.x;
    if (i < e) atomicAdd(&cnt[dst[i] * kR + et[i]], 1u);
}

__global__ __launch_bounds__(1024) void scan_local(
    const unsigned* __restrict__ cnt, unsigned* __restrict__ starts,
    unsigned* __restrict__ bsum, int nseg)
{
    __shared__ unsigned sm[1024];
    int tid = threadIdx.x;
    int g = blockIdx.x * 1024 + tid;
    unsigned x = (g < nseg) ? cnt[g] : 0u;
    sm[tid] = x; __syncthreads();
    for (int off = 1; off < 1024; off <<= 1) {
        unsigned val = sm[tid];
        if (tid >= off) val += sm[tid - off];
        __syncthreads(); sm[tid] = val; __syncthreads();
    }
    if (g < nseg) starts[g] = sm[tid] - x;
    if (tid == 1023) bsum[blockIdx.x] = sm[1023];
}

__global__ __launch_bounds__(1024) void scan_block(unsigned* __restrict__ bsum, int nb) {
    __shared__ unsigned sm[1024];
    int tid = threadIdx.x;
    unsigned x = (tid < nb) ? bsum[tid] : 0u;
    sm[tid] = x; __syncthreads();
    for (int off = 1; off < 1024; off <<= 1) {
        unsigned val = sm[tid];
        if (tid >= off) val += sm[tid - off];
        __syncthreads(); sm[tid] = val; __syncthreads();
    }
    if (tid < nb) bsum[tid] = sm[tid] - x;
}

__global__ void scan_add(unsigned* __restrict__ starts, unsigned* __restrict__ cur,
                         const unsigned* __restrict__ bsum, int nseg, int e) {
    int g = blockIdx.x * 1024 + threadIdx.x;
    if (g < nseg) {
        unsigned v = starts[g] + bsum[blockIdx.x];
        starts[g] = v;
        cur[g] = v;
    }
    if (g == 0) starts[nseg] = (unsigned)e;
}

__global__ void permute_kernel(const int* __restrict__ src, const int* __restrict__ dst,
                               const int* __restrict__ et, unsigned* __restrict__ cur,
                               int* __restrict__ ssrc, int e) {
    int i = blockIdx.x * blockDim.x + threadIdx.x;
    if (i >= e) return;
    int sg = dst[i] * kR + et[i];
    unsigned pos = atomicAdd(&cur[sg], 1u);
    ssrc[pos] = src[i];
}

// ---------------- fused: softmax + aggregation, 4-edge chunks -------------
// one warp per dst; no max-subtraction (logits are O(1), exp safe in fp32);
// chunked gathers + interleaved shuffles break the per-edge serial chain.
__global__ __launch_bounds__(256) void fused_edge_h(
    const unsigned* __restrict__ starts, const int* __restrict__ ssrc,
    const __half2* __restrict__ krel, const __half2* __restrict__ vrel,
    const float* __restrict__ q, const float* __restrict__ rel_pri,
    float* __restrict__ t, int n)
{
    int d = (int)(((size_t)blockIdx.x * blockDim.x + threadIdx.x) >> 5);
    int lane = threadIdx.x & 31;
    if (d >= n) return;
    int h = lane >> 2;

    float4 qv = ((const float4*)(q + (size_t)d * 128))[lane];
    float4 tacc = make_float4(0.f, 0.f, 0.f, 0.f);
    int nrel = 0;
    unsigned base = (unsigned)d * kR;

    for (int r = 0; r < kR; r++) {
        unsigned s0 = starts[base + r];
        unsigned s1 = starts[base + r + 1];
        if (s0 == s1) continue;
        nrel++;
        float pri = rel_pri[r * kH + h] * 0.25f;   // includes 1/sqrt(DK)
        const __half2* kb = krel + (size_t)r * n * 64;
        const __half2* vb = vrel + (size_t)r * n * 64;

        float ssum = 0.f;
        float4 acc = make_float4(0.f, 0.f, 0.f, 0.f);

        for (unsigned i = s0; i < s1; i += 4) {
            unsigned cnt = min(4u, s1 - i);
            int myS = 0;
            if (lane < (int)cnt) myS = ssrc[i + lane];
            int sj[4];
#pragma unroll
            for (int j = 0; j < 4; j++)
                sj[j] = __shfl_sync(0xFFFFFFFFu, myS, j);

            uint2 ku[4], vu[4];
#pragma unroll
            for (int j = 0; j < 4; j++) {
                if (j < (int)cnt) {
                    ku[j] = *(const uint2*)(kb + (size_t)sj[j] * 64 + lane * 2);
                    vu[j] = *(const uint2*)(vb + (size_t)sj[j] * 64 + lane * 2);
                }
            }
            float p[4];
#pragma unroll
            for (int j = 0; j < 4; j++) {
                if (j < (int)cnt) {
                    float2 k01 = __half22float2(*(__half2*)&ku[j].x);
                    float2 k23 = __half22float2(*(__half2*)&ku[j].y);
                    p[j] = k01.x * qv.x + k01.y * qv.y + k23.x * qv.z + k23.y * qv.w;
                }
            }
#pragma unroll
            for (int j = 0; j < 4; j++)
                if (j < (int)cnt) p[j] += __shfl_xor_sync(0xFFFFFFFFu, p[j], 1);
#pragma unroll
            for (int j = 0; j < 4; j++)
                if (j < (int)cnt) p[j] += __shfl_xor_sync(0xFFFFFFFFu, p[j], 2);
#pragma unroll
            for (int j = 0; j < 4; j++) {
                if (j < (int)cnt) {
                    float w = __expf(p[j] * pri);
                    float2 v01 = __half22float2(*(__half2*)&vu[j].x);
                    float2 v23 = __half22float2(*(__half2*)&vu[j].y);
                    ssum += w;
                    acc.x += w * v01.x;
                    acc.y += w * v01.y;
                    acc.z += w * v23.x;
                    acc.w += w * v23.y;
                }
            }
        }
        float inv = 1.f / ssum;
        tacc.x += acc.x * inv;
        tacc.y += acc.y * inv;
        tacc.z += acc.z * inv;
        tacc.w += acc.w * inv;
    }
    float ninv = 1.f / (float)max(nrel, 1);
    ((float4*)(t + (size_t)d * 128))[lane] =
        make_float4(tacc.x * ninv, tacc.y * ninv, tacc.z * ninv, tacc.w * ninv);
}

// ---------------- launch ---------------------------------------------------
extern "C" void kernel_launch(void* const* d_in, const int* in_sizes, int n_in,
                              void* d_out, int out_size) {
    const float* src_h   = (const float*)d_in[0];
    const float* dst_h   = (const float*)d_in[1];
    const float* Wk      = (const float*)d_in[2];
    const float* bk      = (const float*)d_in[3];
    const float* Wq      = (const float*)d_in[4];
    const float* bq      = (const float*)d_in[5];
    const float* Wv      = (const float*)d_in[6];
    const float* bv      = (const float*)d_in[7];
    const float* Wa      = (const float*)d_in[8];
    const float* ba      = (const float*)d_in[9];
    const float* rel_pri = (const float*)d_in[10];
    const float* rel_att = (const float*)d_in[11];
    const float* rel_msg = (const float*)d_in[12];
    const float* skip    = (const float*)d_in[13];
    const int* src_idx   = (const int*)d_in[14];
    const int* dst_idx   = (const int*)d_in[15];
    const int* etype     = (const int*)d_in[16];
    float* out = (float*)d_out;

    int n = in_sizes[0] / kD;
    int e = in_sizes[14];
    int nseg = n * kR;

    float* pool = nullptr;
    cudaGetSymbolAddress((void**)&pool, g_pool);
    float* pq    = pool + OFF_Q;
    float* pk    = pool + OFF_K;
    float* pv    = pool + OFF_V;
    float* pt    = pool + OFF_T;
    __half2* pkrel = (__half2*)(pool + OFF_KRELH);
    __half2* pvrel = (__half2*)(pool + OFF_VRELH);
    unsigned* pcnt  = (unsigned*)(pool + OFF_CNT);
    unsigned* pcur  = (unsigned*)(pool + OFF_CUR);
    unsigned* pbsum = (unsigned*)(pool + OFF_BSUM);
    int* pssrc      = (int*)(pool + OFF_SSRC);

    int gemm_blocks = (n + 127) / 128;
    int nb = (nseg + 1023) / 1024;

    // counting sort by (dst, rel)
    zero_cnt<<<(nseg + 256) / 256, 256>>>(pcnt, nseg);
    hist_kernel<<<(e + 255) / 256, 256>>>(dst_idx, etype, pcnt, e);
    scan_local<<<nb, 1024>>>(pcnt, pcnt, pbsum, nseg);
    scan_block<<<1, 1024>>>(pbsum, nb);
    scan_add<<<nb, 1024>>>(pcnt, pcur, pbsum, nseg, e);
    permute_kernel<<<(e + 255) / 256, 256>>>(src_idx, dst_idx, etype, pcur, pssrc, e);

    // projections + relation transforms (fp16 out)
    gemm_out128<<<gemm_blocks, 256>>>(dst_h, Wq, bq, nullptr, nullptr, pq, n, 0);
    gemm_out128<<<gemm_blocks, 256>>>(src_h, Wk, bk, nullptr, nullptr, pk, n, 0);
    gemm_out128<<<gemm_blocks, 256>>>(src_h, Wv, bv, nullptr, nullptr, pv, n, 0);
    rel_transform_h<<<(n + RT_TILE - 1) / RT_TILE, 256>>>(pk, pv, rel_att, rel_msg,
                                                          pkrel, pvrel, n);

    // fused attention + softmax + aggregation
    fused_edge_h<<<((size_t)n * 32 + 255) / 256, 256>>>(pcnt, pssrc, pkrel, pvrel,
                                                        pq, rel_pri, pt, n);

    // output projection + skip
    gemm_out128<<<gemm_blocks, 256>>>(pt, Wa, ba, dst_h, skip, out, n, 1);
}

// round 8
// speedup vs baseline: 1.3237x; 1.3237x over previous
#include <cuda_runtime.h>
#include <cuda_fp16.h>
#include <cstdint>

// Problem constants
#define kR 8
#define kH 8
#define kDK 16
#define kD 128   // IN_DIM == OUT_DIM

// ---------------- scratch layout (single __device__ pool, float units) ----
//  q      fp32 [N,128]        @ 0          (6.4M)
//  k_h    fp16 [N,128]        @ 6.4M       (3.2M f32)
//  v_h    fp16 [N,128]        @ 9.6M       (3.2M f32)
//  t      fp32 [N,128]        @ 12.8M      (6.4M)
//  qrel_h fp16 [R,N,128]      @ 19.2M      (25.6M f32)
//  msp_h  fp16 packed rel_msg @ 44.8M      (8192 f32)
//  cnt / cur / bsum / ssrc
#define OFF_Q     0ull
#define OFF_KH    6400000ull
#define OFF_VH    9600000ull
#define OFF_T     12800000ull
#define OFF_QRELH 19200000ull
#define OFF_MSP   44800000ull
#define OFF_CNT   44810000ull
#define OFF_CUR   45310000ull
#define OFF_BSUM  45810000ull
#define OFF_SSRC  45820000ull
#define POOL_SZ   47500000ull

__device__ float g_pool[POOL_SZ];

// ---------------- SIMT sgemm: C[n,128] = A[n,128] @ W[128,128]^T + bias ----
// Ch != nullptr: write fp16 to Ch instead of fp32 to C.
// fuse==1: C = alpha*(AB^T+bias) + (1-alpha)*S,  alpha = sigmoid(skip[0])
__global__ __launch_bounds__(256) void gemm_out128(
    const float* __restrict__ A, const float* __restrict__ W,
    const float* __restrict__ bias, const float* __restrict__ S,
    const float* __restrict__ skipv, float* __restrict__ C,
    __half2* __restrict__ Ch, int n, int fuse)
{
    __shared__ float As[8][128];
    __shared__ float Bs[8][128];
    int row0 = blockIdx.x * 128;
    int tid = threadIdx.x;
    int tr = (tid >> 4) << 3;
    int tc = (tid & 15) << 3;
    float acc[8][8];
#pragma unroll
    for (int i = 0; i < 8; i++)
#pragma unroll
        for (int j = 0; j < 8; j++) acc[i][j] = 0.f;

    int li = tid >> 1;
    int lk = (tid & 1) << 2;
    for (int k0 = 0; k0 < 128; k0 += 8) {
        float4 a4 = make_float4(0.f, 0.f, 0.f, 0.f);
        if (row0 + li < n)
            a4 = *(const float4*)(A + (size_t)(row0 + li) * 128 + k0 + lk);
        As[lk + 0][li] = a4.x; As[lk + 1][li] = a4.y;
        As[lk + 2][li] = a4.z; As[lk + 3][li] = a4.w;
        float4 b4 = *(const float4*)(W + (size_t)li * 128 + k0 + lk);
        Bs[lk + 0][li] = b4.x; Bs[lk + 1][li] = b4.y;
        Bs[lk + 2][li] = b4.z; Bs[lk + 3][li] = b4.w;
        __syncthreads();
#pragma unroll
        for (int kk = 0; kk < 8; kk++) {
            float ar[8], br[8];
#pragma unroll
            for (int i = 0; i < 8; i++) ar[i] = As[kk][tr + i];
#pragma unroll
            for (int j = 0; j < 8; j++) br[j] = Bs[kk][tc + j];
#pragma unroll
            for (int i = 0; i < 8; i++)
#pragma unroll
                for (int j = 0; j < 8; j++) acc[i][j] += ar[i] * br[j];
        }
        __syncthreads();
    }
    float alpha = 1.f, beta = 0.f;
    if (fuse) {
        float sv = skipv[0];
        alpha = 1.f / (1.f + expf(-sv));
        beta = 1.f - alpha;
    }
#pragma unroll
    for (int i = 0; i < 8; i++) {
        int r = row0 + tr + i;
        if (r >= n) break;
#pragma unroll
        for (int j = 0; j < 8; j += 2) {
            int c = tc + j;
            float v0 = acc[i][j] + bias[c];
            float v1 = acc[i][j + 1] + bias[c + 1];
            if (Ch) {
                Ch[(size_t)r * 64 + (c >> 1)] = __floats2half2_rn(v0, v1);
            } else {
                if (fuse) {
                    v0 = alpha * v0 + beta * S[(size_t)r * 128 + c];
                    v1 = alpha * v1 + beta * S[(size_t)r * 128 + c + 1];
                }
                C[(size_t)r * 128 + c] = v0;
                C[(size_t)r * 128 + c + 1] = v1;
            }
        }
    }
}

// ---------------- qrel transform: qrel[r,n,h,d] = sum_e A[r,h,d,e] q[n,h,e] -
#define RT_TILE 32
__global__ __launch_bounds__(256) void qrel_transform(
    const float* __restrict__ q, const float* __restrict__ ratt,
    __half2* __restrict__ qrel, int n)
{
    __shared__ float qs[RT_TILE][128];
    __shared__ float mt[2048];   // mt[e*128 + (h*16+d)] = A[r,h,d,e]
    int node0 = blockIdx.x * RT_TILE;
    int tid = threadIdx.x;
    for (int i = tid; i < RT_TILE * 32; i += 256) {
        int nd = i >> 5, c4 = i & 31;
        if (node0 + nd < n)
            ((float4*)qs[nd])[c4] = ((const float4*)(q + (size_t)(node0 + nd) * 128))[c4];
    }
    int cp = tid & 63;      // half2 column 0..63
    int c0 = cp << 1;       // = 16h + d0 (even)
    int h = c0 >> 4;
    int nsub = tid >> 6;
    for (int r = 0; r < kR; r++) {
        __syncthreads();
        for (int i = tid; i < 2048; i += 256) {
            // i = (h*16+d)*16 + e  ->  mt[e*128 + h*16+d]
            int hd = i >> 4, e = i & 15;
            mt[e * 128 + hd] = ratt[r * 2048 + i];
        }
        __syncthreads();
        for (int nd = nsub; nd < RT_TILE; nd += 4) {
            int gn = node0 + nd;
            if (gn >= n) break;
            float a0 = 0.f, a1 = 0.f;
#pragma unroll
            for (int e = 0; e < 16; e++) {
                float qv = qs[nd][h * 16 + e];
                float2 m2 = *(const float2*)(mt + e * 128 + c0);
                a0 += qv * m2.x;
                a1 += qv * m2.y;
            }
            qrel[((size_t)r * n + gn) * 64 + cp] = __floats2half2_rn(a0, a1);
        }
    }
}

// ---------------- pack rel_msg into fp16 lane-major layout ----------------
// msp[r][d][lane][i] = rel_msg[r][h=lane>>2][d][e'=4*(lane&3)+i]
__global__ void pack_msg(const float* __restrict__ rmsg, __half* __restrict__ msp) {
    int r = blockIdx.x;
    for (int t = threadIdx.x; t < 2048; t += 256) {
        int d = t >> 7;
        int lane = (t >> 2) & 31;
        int i = t & 3;
        int h = lane >> 2;
        int ep = ((lane & 3) << 2) + i;
        float val = rmsg[((r * kH + h) * 16 + d) * 16 + ep];
        msp[r * 2048 + d * 128 + lane * 4 + i] = __float2half(val);
    }
}

// ---------------- counting sort by seg = dst*8 + etype --------------------
__global__ void zero_cnt(unsigned* __restrict__ cnt, int nseg) {
    int i = blockIdx.x * blockDim.x + threadIdx.x;
    if (i <= nseg) cnt[i] = 0u;
}

__global__ void hist_kernel(const int* __restrict__ dst, const int* __restrict__ et,
                            unsigned* __restrict__ cnt, int e) {
    int i = blockIdx.x * blockDim.x + threadIdx.x;
    if (i < e) atomicAdd(&cnt[dst[i] * kR + et[i]], 1u);
}

__global__ __launch_bounds__(1024) void scan_local(
    const unsigned* __restrict__ cnt, unsigned* __restrict__ starts,
    unsigned* __restrict__ bsum, int nseg)
{
    __shared__ unsigned sm[1024];
    int tid = threadIdx.x;
    int g = blockIdx.x * 1024 + tid;
    unsigned x = (g < nseg) ? cnt[g] : 0u;
    sm[tid] = x; __syncthreads();
    for (int off = 1; off < 1024; off <<= 1) {
        unsigned val = sm[tid];
        if (tid >= off) val += sm[tid - off];
        __syncthreads(); sm[tid] = val; __syncthreads();
    }
    if (g < nseg) starts[g] = sm[tid] - x;
    if (tid == 1023) bsum[blockIdx.x] = sm[1023];
}

__global__ __launch_bounds__(1024) void scan_block(unsigned* __restrict__ bsum, int nb) {
    __shared__ unsigned sm[1024];
    int tid = threadIdx.x;
    unsigned x = (tid < nb) ? bsum[tid] : 0u;
    sm[tid] = x; __syncthreads();
    for (int off = 1; off < 1024; off <<= 1) {
        unsigned val = sm[tid];
        if (tid >= off) val += sm[tid - off];
        __syncthreads(); sm[tid] = val; __syncthreads();
    }
    if (tid < nb) bsum[tid] = sm[tid] - x;
}

__global__ void scan_add(unsigned* __restrict__ starts, unsigned* __restrict__ cur,
                         const unsigned* __restrict__ bsum, int nseg, int e) {
    int g = blockIdx.x * 1024 + threadIdx.x;
    if (g < nseg) {
        unsigned v = starts[g] + bsum[blockIdx.x];
        starts[g] = v;
        cur[g] = v;
    }
    if (g == 0) starts[nseg] = (unsigned)e;
}

__global__ void permute_kernel(const int* __restrict__ src, const int* __restrict__ dst,
                               const int* __restrict__ et, unsigned* __restrict__ cur,
                               int* __restrict__ ssrc, int e) {
    int i = blockIdx.x * blockDim.x + threadIdx.x;
    if (i >= e) return;
    int sg = dst[i] * kR + et[i];
    unsigned pos = atomicAdd(&cur[sg], 1u);
    ssrc[pos] = src[i];
}

// ---------------- fused edge pass: gather raw k/v (L2-resident), ----------
// per-segment qrel dot + softmax, per-segment M-apply from smem.
__global__ __launch_bounds__(512) void fused_edge2(
    const unsigned* __restrict__ starts, const int* __restrict__ ssrc,
    const __half2* __restrict__ kh, const __half2* __restrict__ vh,
    const __half2* __restrict__ qrel, const __half* __restrict__ mspg,
    const float* __restrict__ rel_pri, float* __restrict__ t, int n)
{
    __shared__ __half msm[16384];   // 32KB: [(r*16+d)*32 + lane]*4 + i
    for (int i = threadIdx.x; i < 8192; i += 512)
        ((uint32_t*)msm)[i] = ((const uint32_t*)mspg)[i];
    __syncthreads();

    int d = (int)(((size_t)blockIdx.x * blockDim.x + threadIdx.x) >> 5);
    int lane = threadIdx.x & 31;
    if (d >= n) return;
    int h = lane >> 2;

    float4 t4 = make_float4(0.f, 0.f, 0.f, 0.f);
    int nrel = 0;
    unsigned base = (unsigned)d * kR;

    for (int r = 0; r < kR; r++) {
        unsigned s0 = starts[base + r];
        unsigned s1 = starts[base + r + 1];
        if (s0 == s1) continue;
        nrel++;
        float pri = rel_pri[r * kH + h] * 0.25f;   // includes 1/sqrt(DK)

        // qrel for this (r, dst): lane's 4 d-components
        uint2 qu = *(const uint2*)(qrel + ((size_t)r * n + d) * 64 + lane * 2);
        float2 q01 = __half22float2(*(__half2*)&qu.x);
        float2 q23 = __half22float2(*(__half2*)&qu.y);

        float ssum = 0.f;
        float4 acc = make_float4(0.f, 0.f, 0.f, 0.f);

        int src = ssrc[s0];
        uint2 ku = *(const uint2*)(kh + (size_t)src * 64 + lane * 2);
        uint2 vu = *(const uint2*)(vh + (size_t)src * 64 + lane * 2);
        for (unsigned i = s0; i < s1; i++) {
            uint2 cku = ku, cvu = vu;
            if (i + 1 < s1) {
                int ns = ssrc[i + 1];
                ku = *(const uint2*)(kh + (size_t)ns * 64 + lane * 2);
                vu = *(const uint2*)(vh + (size_t)ns * 64 + lane * 2);
            }
            float2 k01 = __half22float2(*(__half2*)&cku.x);
            float2 k23 = __half22float2(*(__half2*)&cku.y);
            float p = k01.x * q01.x + k01.y * q01.y + k23.x * q23.x + k23.y * q23.y;
            p += __shfl_xor_sync(0xFFFFFFFFu, p, 1);
            p += __shfl_xor_sync(0xFFFFFFFFu, p, 2);
            float w = __expf(p * pri);
            float2 v01 = __half22float2(*(__half2*)&cvu.x);
            float2 v23 = __half22float2(*(__half2*)&cvu.y);
            ssum += w;
            acc.x += w * v01.x;
            acc.y += w * v01.y;
            acc.z += w * v23.x;
            acc.w += w * v23.y;
        }
        float inv = 1.f / ssum;
        float va[4] = {acc.x * inv, acc.y * inv, acc.z * inv, acc.w * inv};

        // apply M_r: t_e' += sum_d va[d] * M[d][e']  (per head)
#pragma unroll
        for (int dd = 0; dd < 16; dd++) {
            float vd = __shfl_sync(0xFFFFFFFFu, va[dd & 3], (h << 2) | (dd >> 2));
            uint2 mu = *(const uint2*)(msm + (((r * 16 + dd) * 32) + lane) * 4);
            float2 m01 = __half22float2(*(__half2*)&mu.x);
            float2 m23 = __half22float2(*(__half2*)&mu.y);
            t4.x += vd * m01.x;
            t4.y += vd * m01.y;
            t4.z += vd * m23.x;
            t4.w += vd * m23.y;
        }
    }
    float ninv = 1.f / (float)max(nrel, 1);
    ((float4*)(t + (size_t)d * 128))[lane] =
        make_float4(t4.x * ninv, t4.y * ninv, t4.z * ninv, t4.w * ninv);
}

// ---------------- launch ---------------------------------------------------
extern "C" void kernel_launch(void* const* d_in, const int* in_sizes, int n_in,
                              void* d_out, int out_size) {
    const float* src_h   = (const float*)d_in[0];
    const float* dst_h   = (const float*)d_in[1];
    const float* Wk      = (const float*)d_in[2];
    const float* bk      = (const float*)d_in[3];
    const float* Wq      = (const float*)d_in[4];
    const float* bq      = (const float*)d_in[5];
    const float* Wv      = (const float*)d_in[6];
    const float* bv      = (const float*)d_in[7];
    const float* Wa      = (const float*)d_in[8];
    const float* ba      = (const float*)d_in[9];
    const float* rel_pri = (const float*)d_in[10];
    const float* rel_att = (const float*)d_in[11];
    const float* rel_msg = (const float*)d_in[12];
    const float* skip    = (const float*)d_in[13];
    const int* src_idx   = (const int*)d_in[14];
    const int* dst_idx   = (const int*)d_in[15];
    const int* etype     = (const int*)d_in[16];
    float* out = (float*)d_out;

    int n = in_sizes[0] / kD;
    int e = in_sizes[14];
    int nseg = n * kR;

    float* pool = nullptr;
    cudaGetSymbolAddress((void**)&pool, g_pool);
    float* pq      = pool + OFF_Q;
    __half2* pkh   = (__half2*)(pool + OFF_KH);
    __half2* pvh   = (__half2*)(pool + OFF_VH);
    float* pt      = pool + OFF_T;
    __half2* pqrel = (__half2*)(pool + OFF_QRELH);
    __half* pmsp   = (__half*)(pool + OFF_MSP);
    unsigned* pcnt  = (unsigned*)(pool + OFF_CNT);
    unsigned* pcur  = (unsigned*)(pool + OFF_CUR);
    unsigned* pbsum = (unsigned*)(pool + OFF_BSUM);
    int* pssrc      = (int*)(pool + OFF_SSRC);

    int gemm_blocks = (n + 127) / 128;
    int nb = (nseg + 1023) / 1024;

    // counting sort by (dst, rel)
    zero_cnt<<<(nseg + 256) / 256, 256>>>(pcnt, nseg);
    hist_kernel<<<(e + 255) / 256, 256>>>(dst_idx, etype, pcnt, e);
    scan_local<<<nb, 1024>>>(pcnt, pcnt, pbsum, nseg);
    scan_block<<<1, 1024>>>(pbsum, nb);
    scan_add<<<nb, 1024>>>(pcnt, pcur, pbsum, nseg, e);
    permute_kernel<<<(e + 255) / 256, 256>>>(src_idx, dst_idx, etype, pcur, pssrc, e);

    // pack rel_msg fp16
    pack_msg<<<kR, 256>>>(rel_msg, pmsp);

    // projections: q fp32; k,v fp16
    gemm_out128<<<gemm_blocks, 256>>>(dst_h, Wq, bq, nullptr, nullptr, pq, nullptr, n, 0);
    gemm_out128<<<gemm_blocks, 256>>>(src_h, Wk, bk, nullptr, nullptr, nullptr, pkh, n, 0);
    gemm_out128<<<gemm_blocks, 256>>>(src_h, Wv, bv, nullptr, nullptr, nullptr, pvh, n, 0);

    // qrel = A_r^T q per relation
    qrel_transform<<<(n + RT_TILE - 1) / RT_TILE, 256>>>(pq, rel_att, pqrel, n);

    // fused edge pass
    fused_edge2<<<((size_t)n * 32 + 511) / 512, 512>>>(pcnt, pssrc, pkh, pvh,
                                                       pqrel, pmsp, rel_pri, pt, n);

    // output projection + skip
    gemm_out128<<<gemm_blocks, 256>>>(pt, Wa, ba, dst_h, skip, out, nullptr, n, 1);
}

// round 9
// speedup vs baseline: 1.5888x; 1.2003x over previous
#include <cuda_runtime.h>
#include <cuda_fp16.h>
#include <cstdint>

// Problem constants
#define kR 8
#define kH 8
#define kDK 16
#define kD 128   // IN_DIM == OUT_DIM

// ---------------- scratch layout (single __device__ pool, float units) ----
//  q      fp32 [N,128]        @ 0          (6.4M)
//  k_h    fp16 [N,128]        @ 6.4M       (3.2M f32)
//  v_h    fp16 [N,128]        @ 9.6M       (3.2M f32)
//  t      fp32 [N,128]        @ 12.8M      (6.4M)
//  qrel_h fp16 [R,N,128]      @ 19.2M      (25.6M f32)
//  msp_h  fp16 packed rel_msg @ 44.8M
//  cnt / cur / bsum / ssrc / Wp (packed tf32 weights)
#define OFF_Q     0ull
#define OFF_KH    6400000ull
#define OFF_VH    9600000ull
#define OFF_T     12800000ull
#define OFF_QRELH 19200000ull
#define OFF_MSP   44800000ull
#define OFF_CNT   44810000ull
#define OFF_CUR   45310000ull
#define OFF_BSUM  45810000ull
#define OFF_SSRC  45820000ull
#define OFF_WP    47420000ull   // 4 x 8192 uint2 = 65536 floats
#define POOL_SZ   47500000ull

__device__ float g_pool[POOL_SZ];

// ---------------- tf32 helpers --------------------------------------------
__device__ __forceinline__ unsigned f2tf32(float f) {
    unsigned u;
    asm("cvt.rna.tf32.f32 %0, %1;" : "=r"(u) : "f"(f));
    return u;
}

__device__ __forceinline__ void mma_tf32(float* d, const unsigned* a, uint2 b) {
    asm volatile(
        "mma.sync.aligned.m16n8k8.row.col.f32.tf32.tf32.f32 "
        "{%0,%1,%2,%3}, {%4,%5,%6,%7}, {%8,%9}, {%0,%1,%2,%3};"
        : "+f"(d[0]), "+f"(d[1]), "+f"(d[2]), "+f"(d[3])
        : "r"(a[0]), "r"(a[1]), "r"(a[2]), "r"(a[3]), "r"(b.x), "r"(b.y));
}

// ---------------- pack W[128,128] into fragment-native tf32 layout --------
// Wp[(nt*16+ks)*32 + lane] = {tf32(W[col][k]), tf32(W[col][k+4])},
//   col = nt*8 + (lane>>2), k = ks*8 + (lane&3)
__global__ void pack_w(const float* __restrict__ W, uint2* __restrict__ Wp) {
    int i = blockIdx.x * blockDim.x + threadIdx.x;
    if (i >= 8192) return;
    int nt = i >> 9, ks = (i >> 5) & 15, lane = i & 31;
    int g = lane >> 2, t = lane & 3;
    int col = nt * 8 + g;
    int k = ks * 8 + t;
    uint2 o;
    o.x = f2tf32(W[col * 128 + k]);
    o.y = f2tf32(W[col * 128 + k + 4]);
    Wp[i] = o;
}

// ---------------- tensor-core GEMM: C[n,128] = A[n,128] @ W^T + bias ------
// Wp is the packed tf32 weight. Ch!=nullptr -> fp16 output.
// fuse==1: C = alpha*(AB^T+bias) + (1-alpha)*S, alpha = sigmoid(skip[0])
__global__ __launch_bounds__(256) void gemm_tf32(
    const float* __restrict__ A, const uint2* __restrict__ Wp,
    const float* __restrict__ bias, const float* __restrict__ S,
    const float* __restrict__ skipv, float* __restrict__ C,
    __half2* __restrict__ Ch, int n, int fuse)
{
    int w = threadIdx.x >> 5, lane = threadIdx.x & 31;
    int g = lane >> 2, t = lane & 3;
    int row0 = blockIdx.x * 128 + w * 16;
    int rA = row0 + g;          // rows for a0/a2, c0/c1
    int rB = row0 + g + 8;      // rows for a1/a3, c2/c3
    bool okA = rA < n, okB = rB < n;
    const float* pA = A + (size_t)rA * 128 + t;
    const float* pB = A + (size_t)rB * 128 + t;

    float acc[16][4];
#pragma unroll
    for (int i = 0; i < 16; i++)
#pragma unroll
        for (int j = 0; j < 4; j++) acc[i][j] = 0.f;

#pragma unroll
    for (int ks = 0; ks < 16; ks++) {
        int k0 = ks * 8;
        unsigned a[4];
        a[0] = f2tf32(okA ? pA[k0] : 0.f);
        a[1] = f2tf32(okB ? pB[k0] : 0.f);
        a[2] = f2tf32(okA ? pA[k0 + 4] : 0.f);
        a[3] = f2tf32(okB ? pB[k0 + 4] : 0.f);
#pragma unroll
        for (int nt = 0; nt < 16; nt++) {
            uint2 b = Wp[(nt * 16 + ks) * 32 + lane];
            mma_tf32(acc[nt], a, b);
        }
    }

    float alpha = 1.f, beta = 0.f;
    if (fuse) {
        float sv = skipv[0];
        alpha = 1.f / (1.f + expf(-sv));
        beta = 1.f - alpha;
    }

#pragma unroll
    for (int nt = 0; nt < 16; nt++) {
        int col = nt * 8 + t * 2;
        float2 b2 = *(const float2*)(bias + col);
        float v0 = acc[nt][0] + b2.x;
        float v1 = acc[nt][1] + b2.y;
        float v2 = acc[nt][2] + b2.x;
        float v3 = acc[nt][3] + b2.y;
        if (Ch) {
            if (okA) Ch[(size_t)rA * 64 + (col >> 1)] = __floats2half2_rn(v0, v1);
            if (okB) Ch[(size_t)rB * 64 + (col >> 1)] = __floats2half2_rn(v2, v3);
        } else {
            if (okA) {
                if (fuse) {
                    float2 s2 = *(const float2*)(S + (size_t)rA * 128 + col);
                    v0 = alpha * v0 + beta * s2.x;
                    v1 = alpha * v1 + beta * s2.y;
                }
                *(float2*)(C + (size_t)rA * 128 + col) = make_float2(v0, v1);
            }
            if (okB) {
                if (fuse) {
                    float2 s2 = *(const float2*)(S + (size_t)rB * 128 + col);
                    v2 = alpha * v2 + beta * s2.x;
                    v3 = alpha * v3 + beta * s2.y;
                }
                *(float2*)(C + (size_t)rB * 128 + col) = make_float2(v2, v3);
            }
        }
    }
}

// ---------------- qrel transform: qrel[r,n,h,d] = sum_e A[r,h,d,e] q[n,h,e] -
#define RT_TILE 32
__global__ __launch_bounds__(256) void qrel_transform(
    const float* __restrict__ q, const float* __restrict__ ratt,
    __half2* __restrict__ qrel, int n)
{
    __shared__ float qs[RT_TILE][128];
    __shared__ float mt[2048];   // mt[e*128 + (h*16+d)] = A[r,h,d,e]
    int node0 = blockIdx.x * RT_TILE;
    int tid = threadIdx.x;
    for (int i = tid; i < RT_TILE * 32; i += 256) {
        int nd = i >> 5, c4 = i & 31;
        if (node0 + nd < n)
            ((float4*)qs[nd])[c4] = ((const float4*)(q + (size_t)(node0 + nd) * 128))[c4];
    }
    int cp = tid & 63;      // half2 column 0..63
    int c0 = cp << 1;       // = 16h + d0 (even)
    int h = c0 >> 4;
    int nsub = tid >> 6;
    for (int r = 0; r < kR; r++) {
        __syncthreads();
        for (int i = tid; i < 2048; i += 256) {
            int hd = i >> 4, e = i & 15;
            mt[e * 128 + hd] = ratt[r * 2048 + i];
        }
        __syncthreads();
        for (int nd = nsub; nd < RT_TILE; nd += 4) {
            int gn = node0 + nd;
            if (gn >= n) break;
            float a0 = 0.f, a1 = 0.f;
#pragma unroll
            for (int e = 0; e < 16; e++) {
                float qv = qs[nd][h * 16 + e];
                float2 m2 = *(const float2*)(mt + e * 128 + c0);
                a0 += qv * m2.x;
                a1 += qv * m2.y;
            }
            qrel[((size_t)r * n + gn) * 64 + cp] = __floats2half2_rn(a0, a1);
        }
    }
}

// ---------------- pack rel_msg into fp16 lane-major layout ----------------
__global__ void pack_msg(const float* __restrict__ rmsg, __half* __restrict__ msp) {
    int r = blockIdx.x;
    for (int t = threadIdx.x; t < 2048; t += 256) {
        int d = t >> 7;
        int lane = (t >> 2) & 31;
        int i = t & 3;
        int h = lane >> 2;
        int ep = ((lane & 3) << 2) + i;
        float val = rmsg[((r * kH + h) * 16 + d) * 16 + ep];
        msp[r * 2048 + d * 128 + lane * 4 + i] = __float2half(val);
    }
}

// ---------------- counting sort by seg = dst*8 + etype --------------------
__global__ void zero_cnt(unsigned* __restrict__ cnt, int nseg) {
    int i = blockIdx.x * blockDim.x + threadIdx.x;
    if (i <= nseg) cnt[i] = 0u;
}

__global__ void hist_kernel(const int* __restrict__ dst, const int* __restrict__ et,
                            unsigned* __restrict__ cnt, int e) {
    int i = blockIdx.x * blockDim.x + threadIdx.x;
    if (i < e) atomicAdd(&cnt[dst[i] * kR + et[i]], 1u);
}

__global__ __launch_bounds__(1024) void scan_local(
    const unsigned* __restrict__ cnt, unsigned* __restrict__ starts,
    unsigned* __restrict__ bsum, int nseg)
{
    __shared__ unsigned sm[1024];
    int tid = threadIdx.x;
    int g = blockIdx.x * 1024 + tid;
    unsigned x = (g < nseg) ? cnt[g] : 0u;
    sm[tid] = x; __syncthreads();
    for (int off = 1; off < 1024; off <<= 1) {
        unsigned val = sm[tid];
        if (tid >= off) val += sm[tid - off];
        __syncthreads(); sm[tid] = val; __syncthreads();
    }
    if (g < nseg) starts[g] = sm[tid] - x;
    if (tid == 1023) bsum[blockIdx.x] = sm[1023];
}

__global__ __launch_bounds__(1024) void scan_block(unsigned* __restrict__ bsum, int nb) {
    __shared__ unsigned sm[1024];
    int tid = threadIdx.x;
    unsigned x = (tid < nb) ? bsum[tid] : 0u;
    sm[tid] = x; __syncthreads();
    for (int off = 1; off < 1024; off <<= 1) {
        unsigned val = sm[tid];
        if (tid >= off) val += sm[tid - off];
        __syncthreads(); sm[tid] = val; __syncthreads();
    }
    if (tid < nb) bsum[tid] = sm[tid] - x;
}

__global__ void scan_add(unsigned* __restrict__ starts, unsigned* __restrict__ cur,
                         const unsigned* __restrict__ bsum, int nseg, int e) {
    int g = blockIdx.x * 1024 + threadIdx.x;
    if (g < nseg) {
        unsigned v = starts[g] + bsum[blockIdx.x];
        starts[g] = v;
        cur[g] = v;
    }
    if (g == 0) starts[nseg] = (unsigned)e;
}

__global__ void permute_kernel(const int* __restrict__ src, const int* __restrict__ dst,
                               const int* __restrict__ et, unsigned* __restrict__ cur,
                               int* __restrict__ ssrc, int e) {
    int i = blockIdx.x * blockDim.x + threadIdx.x;
    if (i >= e) return;
    int sg = dst[i] * kR + et[i];
    unsigned pos = atomicAdd(&cur[sg], 1u);
    ssrc[pos] = src[i];
}

// ---------------- fused edge pass: gather raw k/v (L2-resident), ----------
// per-segment qrel dot + softmax, per-segment M-apply from smem.
__global__ __launch_bounds__(512) void fused_edge2(
    const unsigned* __restrict__ starts, const int* __restrict__ ssrc,
    const __half2* __restrict__ kh, const __half2* __restrict__ vh,
    const __half2* __restrict__ qrel, const __half* __restrict__ mspg,
    const float* __restrict__ rel_pri, float* __restrict__ t, int n)
{
    __shared__ __half msm[16384];   // 32KB
    for (int i = threadIdx.x; i < 8192; i += 512)
        ((uint32_t*)msm)[i] = ((const uint32_t*)mspg)[i];
    __syncthreads();

    int d = (int)(((size_t)blockIdx.x * blockDim.x + threadIdx.x) >> 5);
    int lane = threadIdx.x & 31;
    if (d >= n) return;
    int h = lane >> 2;

    float4 t4 = make_float4(0.f, 0.f, 0.f, 0.f);
    int nrel = 0;
    unsigned base = (unsigned)d * kR;

    for (int r = 0; r < kR; r++) {
        unsigned s0 = starts[base + r];
        unsigned s1 = starts[base + r + 1];
        if (s0 == s1) continue;
        nrel++;
        float pri = rel_pri[r * kH + h] * 0.25f;   // includes 1/sqrt(DK)

        uint2 qu = *(const uint2*)(qrel + ((size_t)r * n + d) * 64 + lane * 2);
        float2 q01 = __half22float2(*(__half2*)&qu.x);
        float2 q23 = __half22float2(*(__half2*)&qu.y);

        float ssum = 0.f;
        float4 acc = make_float4(0.f, 0.f, 0.f, 0.f);

        int src = ssrc[s0];
        uint2 ku = *(const uint2*)(kh + (size_t)src * 64 + lane * 2);
        uint2 vu = *(const uint2*)(vh + (size_t)src * 64 + lane * 2);
        for (unsigned i = s0; i < s1; i++) {
            uint2 cku = ku, cvu = vu;
            if (i + 1 < s1) {
                int ns = ssrc[i + 1];
                ku = *(const uint2*)(kh + (size_t)ns * 64 + lane * 2);
                vu = *(const uint2*)(vh + (size_t)ns * 64 + lane * 2);
            }
            float2 k01 = __half22float2(*(__half2*)&cku.x);
            float2 k23 = __half22float2(*(__half2*)&cku.y);
            float p = k01.x * q01.x + k01.y * q01.y + k23.x * q23.x + k23.y * q23.y;
            p += __shfl_xor_sync(0xFFFFFFFFu, p, 1);
            p += __shfl_xor_sync(0xFFFFFFFFu, p, 2);
            float w = __expf(p * pri);
            float2 v01 = __half22float2(*(__half2*)&cvu.x);
            float2 v23 = __half22float2(*(__half2*)&cvu.y);
            ssum += w;
            acc.x += w * v01.x;
            acc.y += w * v01.y;
            acc.z += w * v23.x;
            acc.w += w * v23.y;
        }
        float inv = 1.f / ssum;
        float va[4] = {acc.x * inv, acc.y * inv, acc.z * inv, acc.w * inv};

#pragma unroll
        for (int dd = 0; dd < 16; dd++) {
            float vd = __shfl_sync(0xFFFFFFFFu, va[dd & 3], (h << 2) | (dd >> 2));
            uint2 mu = *(const uint2*)(msm + (((r * 16 + dd) * 32) + lane) * 4);
            float2 m01 = __half22float2(*(__half2*)&mu.x);
            float2 m23 = __half22float2(*(__half2*)&mu.y);
            t4.x += vd * m01.x;
            t4.y += vd * m01.y;
            t4.z += vd * m23.x;
            t4.w += vd * m23.y;
        }
    }
    float ninv = 1.f / (float)max(nrel, 1);
    ((float4*)(t + (size_t)d * 128))[lane] =
        make_float4(t4.x * ninv, t4.y * ninv, t4.z * ninv, t4.w * ninv);
}

// ---------------- launch ---------------------------------------------------
extern "C" void kernel_launch(void* const* d_in, const int* in_sizes, int n_in,
                              void* d_out, int out_size) {
    const float* src_h   = (const float*)d_in[0];
    const float* dst_h   = (const float*)d_in[1];
    const float* Wk      = (const float*)d_in[2];
    const float* bk      = (const float*)d_in[3];
    const float* Wq      = (const float*)d_in[4];
    const float* bq      = (const float*)d_in[5];
    const float* Wv      = (const float*)d_in[6];
    const float* bv      = (const float*)d_in[7];
    const float* Wa      = (const float*)d_in[8];
    const float* ba      = (const float*)d_in[9];
    const float* rel_pri = (const float*)d_in[10];
    const float* rel_att = (const float*)d_in[11];
    const float* rel_msg = (const float*)d_in[12];
    const float* skip    = (const float*)d_in[13];
    const int* src_idx   = (const int*)d_in[14];
    const int* dst_idx   = (const int*)d_in[15];
    const int* etype     = (const int*)d_in[16];
    float* out = (float*)d_out;

    int n = in_sizes[0] / kD;
    int e = in_sizes[14];
    int nseg = n * kR;

    float* pool = nullptr;
    cudaGetSymbolAddress((void**)&pool, g_pool);
    float* pq      = pool + OFF_Q;
    __half2* pkh   = (__half2*)(pool + OFF_KH);
    __half2* pvh   = (__half2*)(pool + OFF_VH);
    float* pt      = pool + OFF_T;
    __half2* pqrel = (__half2*)(pool + OFF_QRELH);
    __half* pmsp   = (__half*)(pool + OFF_MSP);
    unsigned* pcnt  = (unsigned*)(pool + OFF_CNT);
    unsigned* pcur  = (unsigned*)(pool + OFF_CUR);
    unsigned* pbsum = (unsigned*)(pool + OFF_BSUM);
    int* pssrc      = (int*)(pool + OFF_SSRC);
    uint2* pWq = (uint2*)(pool + OFF_WP);
    uint2* pWk = pWq + 8192;
    uint2* pWv = pWq + 16384;
    uint2* pWa = pWq + 24576;

    int gemm_blocks = (n + 127) / 128;
    int nb = (nseg + 1023) / 1024;

    // pack weights (tf32 fragment layout) + rel_msg fp16
    pack_w<<<32, 256>>>(Wq, pWq);
    pack_w<<<32, 256>>>(Wk, pWk);
    pack_w<<<32, 256>>>(Wv, pWv);
    pack_w<<<32, 256>>>(Wa, pWa);
    pack_msg<<<kR, 256>>>(rel_msg, pmsp);

    // counting sort by (dst, rel)
    zero_cnt<<<(nseg + 256) / 256, 256>>>(pcnt, nseg);
    hist_kernel<<<(e + 255) / 256, 256>>>(dst_idx, etype, pcnt, e);
    scan_local<<<nb, 1024>>>(pcnt, pcnt, pbsum, nseg);
    scan_block<<<1, 1024>>>(pbsum, nb);
    scan_add<<<nb, 1024>>>(pcnt, pcur, pbsum, nseg, e);
    permute_kernel<<<(e + 255) / 256, 256>>>(src_idx, dst_idx, etype, pcur, pssrc, e);

    // projections (tensor cores): q fp32; k,v fp16
    gemm_tf32<<<gemm_blocks, 256>>>(dst_h, pWq, bq, nullptr, nullptr, pq, nullptr, n, 0);
    gemm_tf32<<<gemm_blocks, 256>>>(src_h, pWk, bk, nullptr, nullptr, nullptr, pkh, n, 0);
    gemm_tf32<<<gemm_blocks, 256>>>(src_h, pWv, bv, nullptr, nullptr, nullptr, pvh, n, 0);

    // qrel = A_r^T q per relation
    qrel_transform<<<(n + RT_TILE - 1) / RT_TILE, 256>>>(pq, rel_att, pqrel, n);

    // fused edge pass
    fused_edge2<<<((size_t)n * 32 + 511) / 512, 512>>>(pcnt, pssrc, pkh, pvh,
                                                       pqrel, pmsp, rel_pri, pt, n);

    // output projection + skip (tensor cores)
    gemm_tf32<<<gemm_blocks, 256>>>(pt, pWa, ba, dst_h, skip, out, nullptr, n, 1);
}

// round 10
// speedup vs baseline: 1.6854x; 1.0608x over previous
#include <cuda_runtime.h>
#include <cuda_fp16.h>
#include <cstdint>

// Problem constants
#define kR 8
#define kH 8
#define kDK 16
#define kD 128   // IN_DIM == OUT_DIM

// ---------------- scratch layout (single __device__ pool, float units) ----
#define OFF_Q     0ull
#define OFF_KH    6400000ull
#define OFF_VH    9600000ull
#define OFF_T     12800000ull
#define OFF_QRELH 19200000ull
#define OFF_MSP   44800000ull
#define OFF_CNT   44810000ull
#define OFF_CUR   45310000ull
#define OFF_BSUM  45810000ull
#define OFF_SSRC  45820000ull
#define OFF_WP    47420000ull   // 4 x 8192 uint2 = 65536 floats
#define POOL_SZ   47500000ull

__device__ float g_pool[POOL_SZ];

// ---------------- tf32 helpers --------------------------------------------
__device__ __forceinline__ unsigned f2tf32(float f) {
    unsigned u;
    asm("cvt.rna.tf32.f32 %0, %1;" : "=r"(u) : "f"(f));
    return u;
}

__device__ __forceinline__ void mma_tf32(float* d, const unsigned* a, uint2 b) {
    asm volatile(
        "mma.sync.aligned.m16n8k8.row.col.f32.tf32.tf32.f32 "
        "{%0,%1,%2,%3}, {%4,%5,%6,%7}, {%8,%9}, {%0,%1,%2,%3};"
        : "+f"(d[0]), "+f"(d[1]), "+f"(d[2]), "+f"(d[3])
        : "r"(a[0]), "r"(a[1]), "r"(a[2]), "r"(a[3]), "r"(b.x), "r"(b.y));
}

// ---------------- pack W[128,128] into fragment-native tf32 layout --------
__global__ void pack_w(const float* __restrict__ W, uint2* __restrict__ Wp) {
    int i = blockIdx.x * blockDim.x + threadIdx.x;
    if (i >= 8192) return;
    int nt = i >> 9, ks = (i >> 5) & 15, lane = i & 31;
    int g = lane >> 2, t = lane & 3;
    int col = nt * 8 + g;
    int k = ks * 8 + t;
    uint2 o;
    o.x = f2tf32(W[col * 128 + k]);
    o.y = f2tf32(W[col * 128 + k + 4]);
    Wp[i] = o;
}

// ---------------- tensor-core GEMM (smem-staged A) -------------------------
#define AST 136   // row stride in floats: 136*4B=544B (16B-aligned), banks (8g+t)%32 distinct
#define GEMM_SMEM (128 * AST * 4)

__global__ __launch_bounds__(256) void gemm_tf32(
    const float* __restrict__ A, const uint2* __restrict__ Wp,
    const float* __restrict__ bias, const float* __restrict__ S,
    const float* __restrict__ skipv, float* __restrict__ C,
    __half2* __restrict__ Ch, int n, int fuse)
{
    extern __shared__ float As[];
    int tid = threadIdx.x;
    int rbase = blockIdx.x * 128;

    // coalesced tile load, zero-fill tail rows
    for (int i = tid; i < 128 * 32; i += 256) {
        int row = i >> 5, c4 = i & 31;
        float4 v = make_float4(0.f, 0.f, 0.f, 0.f);
        if (rbase + row < n)
            v = *(const float4*)(A + (size_t)(rbase + row) * 128 + c4 * 4);
        *(float4*)(As + row * AST + c4 * 4) = v;
    }
    __syncthreads();

    int w = tid >> 5, lane = tid & 31;
    int g = lane >> 2, t = lane & 3;
    int rowA = w * 16 + g, rowB = rowA + 8;
    int rA = rbase + rowA, rB = rbase + rowB;
    bool okA = rA < n, okB = rB < n;
    const float* sA = As + rowA * AST + t;
    const float* sB = As + rowB * AST + t;

    float acc[16][4];
#pragma unroll
    for (int i = 0; i < 16; i++)
#pragma unroll
        for (int j = 0; j < 4; j++) acc[i][j] = 0.f;

#pragma unroll
    for (int ks = 0; ks < 16; ks++) {
        int k0 = ks * 8;
        unsigned a[4];
        a[0] = f2tf32(sA[k0]);
        a[1] = f2tf32(sB[k0]);
        a[2] = f2tf32(sA[k0 + 4]);
        a[3] = f2tf32(sB[k0 + 4]);
#pragma unroll
        for (int nt = 0; nt < 16; nt++) {
            uint2 b = Wp[(nt * 16 + ks) * 32 + lane];
            mma_tf32(acc[nt], a, b);
        }
    }

    float alpha = 1.f, beta = 0.f;
    if (fuse) {
        float sv = skipv[0];
        alpha = 1.f / (1.f + expf(-sv));
        beta = 1.f - alpha;
    }

#pragma unroll
    for (int nt = 0; nt < 16; nt++) {
        int col = nt * 8 + t * 2;
        float2 b2 = *(const float2*)(bias + col);
        float v0 = acc[nt][0] + b2.x;
        float v1 = acc[nt][1] + b2.y;
        float v2 = acc[nt][2] + b2.x;
        float v3 = acc[nt][3] + b2.y;
        if (Ch) {
            if (okA) Ch[(size_t)rA * 64 + (col >> 1)] = __floats2half2_rn(v0, v1);
            if (okB) Ch[(size_t)rB * 64 + (col >> 1)] = __floats2half2_rn(v2, v3);
        } else {
            if (okA) {
                if (fuse) {
                    float2 s2 = *(const float2*)(S + (size_t)rA * 128 + col);
                    v0 = alpha * v0 + beta * s2.x;
                    v1 = alpha * v1 + beta * s2.y;
                }
                *(float2*)(C + (size_t)rA * 128 + col) = make_float2(v0, v1);
            }
            if (okB) {
                if (fuse) {
                    float2 s2 = *(const float2*)(S + (size_t)rB * 128 + col);
                    v2 = alpha * v2 + beta * s2.x;
                    v3 = alpha * v3 + beta * s2.y;
                }
                *(float2*)(C + (size_t)rB * 128 + col) = make_float2(v2, v3);
            }
        }
    }
}

// ---------------- qrel transform: qrel[r,n,h,d] = sum_e A[r,h,d,e] q[n,h,e] -
#define RT_TILE 32
__global__ __launch_bounds__(256) void qrel_transform(
    const float* __restrict__ q, const float* __restrict__ ratt,
    __half2* __restrict__ qrel, int n)
{
    __shared__ float qs[RT_TILE][128];
    __shared__ float mt[2048];
    int node0 = blockIdx.x * RT_TILE;
    int tid = threadIdx.x;
    for (int i = tid; i < RT_TILE * 32; i += 256) {
        int nd = i >> 5, c4 = i & 31;
        if (node0 + nd < n)
            ((float4*)qs[nd])[c4] = ((const float4*)(q + (size_t)(node0 + nd) * 128))[c4];
    }
    int cp = tid & 63;
    int c0 = cp << 1;
    int h = c0 >> 4;
    int nsub = tid >> 6;
    for (int r = 0; r < kR; r++) {
        __syncthreads();
        for (int i = tid; i < 2048; i += 256) {
            int hd = i >> 4, e = i & 15;
            mt[e * 128 + hd] = ratt[r * 2048 + i];
        }
        __syncthreads();
        for (int nd = nsub; nd < RT_TILE; nd += 4) {
            int gn = node0 + nd;
            if (gn >= n) break;
            float a0 = 0.f, a1 = 0.f;
#pragma unroll
            for (int e = 0; e < 16; e++) {
                float qv = qs[nd][h * 16 + e];
                float2 m2 = *(const float2*)(mt + e * 128 + c0);
                a0 += qv * m2.x;
                a1 += qv * m2.y;
            }
            qrel[((size_t)r * n + gn) * 64 + cp] = __floats2half2_rn(a0, a1);
        }
    }
}

// ---------------- pack rel_msg into fp16 lane-major layout ----------------
__global__ void pack_msg(const float* __restrict__ rmsg, __half* __restrict__ msp) {
    int r = blockIdx.x;
    for (int t = threadIdx.x; t < 2048; t += 256) {
        int d = t >> 7;
        int lane = (t >> 2) & 31;
        int i = t & 3;
        int h = lane >> 2;
        int ep = ((lane & 3) << 2) + i;
        float val = rmsg[((r * kH + h) * 16 + d) * 16 + ep];
        msp[r * 2048 + d * 128 + lane * 4 + i] = __float2half(val);
    }
}

// ---------------- counting sort by seg = dst*8 + etype --------------------
__global__ void zero_cnt(unsigned* __restrict__ cnt, int nseg) {
    int i = blockIdx.x * blockDim.x + threadIdx.x;
    if (i <= nseg) cnt[i] = 0u;
}

__global__ void hist_kernel(const int* __restrict__ dst, const int* __restrict__ et,
                            unsigned* __restrict__ cnt, int e) {
    int i = blockIdx.x * blockDim.x + threadIdx.x;
    if (i < e) atomicAdd(&cnt[dst[i] * kR + et[i]], 1u);
}

__global__ __launch_bounds__(1024) void scan_local(
    const unsigned* __restrict__ cnt, unsigned* __restrict__ starts,
    unsigned* __restrict__ bsum, int nseg)
{
    __shared__ unsigned sm[1024];
    int tid = threadIdx.x;
    int g = blockIdx.x * 1024 + tid;
    unsigned x = (g < nseg) ? cnt[g] : 0u;
    sm[tid] = x; __syncthreads();
    for (int off = 1; off < 1024; off <<= 1) {
        unsigned val = sm[tid];
        if (tid >= off) val += sm[tid - off];
        __syncthreads(); sm[tid] = val; __syncthreads();
    }
    if (g < nseg) starts[g] = sm[tid] - x;
    if (tid == 1023) bsum[blockIdx.x] = sm[1023];
}

__global__ __launch_bounds__(1024) void scan_block(unsigned* __restrict__ bsum, int nb) {
    __shared__ unsigned sm[1024];
    int tid = threadIdx.x;
    unsigned x = (tid < nb) ? bsum[tid] : 0u;
    sm[tid] = x; __syncthreads();
    for (int off = 1; off < 1024; off <<= 1) {
        unsigned val = sm[tid];
        if (tid >= off) val += sm[tid - off];
        __syncthreads(); sm[tid] = val; __syncthreads();
    }
    if (tid < nb) bsum[tid] = sm[tid] - x;
}

__global__ void scan_add(unsigned* __restrict__ starts, unsigned* __restrict__ cur,
                         const unsigned* __restrict__ bsum, int nseg, int e) {
    int g = blockIdx.x * 1024 + threadIdx.x;
    if (g < nseg) {
        unsigned v = starts[g] + bsum[blockIdx.x];
        starts[g] = v;
        cur[g] = v;
    }
    if (g == 0) starts[nseg] = (unsigned)e;
}

__global__ void permute_kernel(const int* __restrict__ src, const int* __restrict__ dst,
                               const int* __restrict__ et, unsigned* __restrict__ cur,
                               int* __restrict__ ssrc, int e) {
    int i = blockIdx.x * blockDim.x + threadIdx.x;
    if (i >= e) return;
    int sg = dst[i] * kR + et[i];
    unsigned pos = atomicAdd(&cur[sg], 1u);
    ssrc[pos] = src[i];
}

// ---------------- fused edge pass (unchanged from R8) ---------------------
__global__ __launch_bounds__(512) void fused_edge2(
    const unsigned* __restrict__ starts, const int* __restrict__ ssrc,
    const __half2* __restrict__ kh, const __half2* __restrict__ vh,
    const __half2* __restrict__ qrel, const __half* __restrict__ mspg,
    const float* __restrict__ rel_pri, float* __restrict__ t, int n)
{
    __shared__ __half msm[16384];
    for (int i = threadIdx.x; i < 8192; i += 512)
        ((uint32_t*)msm)[i] = ((const uint32_t*)mspg)[i];
    __syncthreads();

    int d = (int)(((size_t)blockIdx.x * blockDim.x + threadIdx.x) >> 5);
    int lane = threadIdx.x & 31;
    if (d >= n) return;
    int h = lane >> 2;

    float4 t4 = make_float4(0.f, 0.f, 0.f, 0.f);
    int nrel = 0;
    unsigned base = (unsigned)d * kR;

    for (int r = 0; r < kR; r++) {
        unsigned s0 = starts[base + r];
        unsigned s1 = starts[base + r + 1];
        if (s0 == s1) continue;
        nrel++;
        float pri = rel_pri[r * kH + h] * 0.25f;

        uint2 qu = *(const uint2*)(qrel + ((size_t)r * n + d) * 64 + lane * 2);
        float2 q01 = __half22float2(*(__half2*)&qu.x);
        float2 q23 = __half22float2(*(__half2*)&qu.y);

        float ssum = 0.f;
        float4 acc = make_float4(0.f, 0.f, 0.f, 0.f);

        int src = ssrc[s0];
        uint2 ku = *(const uint2*)(kh + (size_t)src * 64 + lane * 2);
        uint2 vu = *(const uint2*)(vh + (size_t)src * 64 + lane * 2);
        for (unsigned i = s0; i < s1; i++) {
            uint2 cku = ku, cvu = vu;
            if (i + 1 < s1) {
                int ns = ssrc[i + 1];
                ku = *(const uint2*)(kh + (size_t)ns * 64 + lane * 2);
                vu = *(const uint2*)(vh + (size_t)ns * 64 + lane * 2);
            }
            float2 k01 = __half22float2(*(__half2*)&cku.x);
            float2 k23 = __half22float2(*(__half2*)&cku.y);
            float p = k01.x * q01.x + k01.y * q01.y + k23.x * q23.x + k23.y * q23.y;
            p += __shfl_xor_sync(0xFFFFFFFFu, p, 1);
            p += __shfl_xor_sync(0xFFFFFFFFu, p, 2);
            float w = __expf(p * pri);
            float2 v01 = __half22float2(*(__half2*)&cvu.x);
            float2 v23 = __half22float2(*(__half2*)&cvu.y);
            ssum += w;
            acc.x += w * v01.x;
            acc.y += w * v01.y;
            acc.z += w * v23.x;
            acc.w += w * v23.y;
        }
        float inv = 1.f / ssum;
        float va[4] = {acc.x * inv, acc.y * inv, acc.z * inv, acc.w * inv};

#pragma unroll
        for (int dd = 0; dd < 16; dd++) {
            float vd = __shfl_sync(0xFFFFFFFFu, va[dd & 3], (h << 2) | (dd >> 2));
            uint2 mu = *(const uint2*)(msm + (((r * 16 + dd) * 32) + lane) * 4);
            float2 m01 = __half22float2(*(__half2*)&mu.x);
            float2 m23 = __half22float2(*(__half2*)&mu.y);
            t4.x += vd * m01.x;
            t4.y += vd * m01.y;
            t4.z += vd * m23.x;
            t4.w += vd * m23.y;
        }
    }
    float ninv = 1.f / (float)max(nrel, 1);
    ((float4*)(t + (size_t)d * 128))[lane] =
        make_float4(t4.x * ninv, t4.y * ninv, t4.z * ninv, t4.w * ninv);
}

// ---------------- launch ---------------------------------------------------
extern "C" void kernel_launch(void* const* d_in, const int* in_sizes, int n_in,
                              void* d_out, int out_size) {
    const float* src_h   = (const float*)d_in[0];
    const float* dst_h   = (const float*)d_in[1];
    const float* Wk      = (const float*)d_in[2];
    const float* bk      = (const float*)d_in[3];
    const float* Wq      = (const float*)d_in[4];
    const float* bq      = (const float*)d_in[5];
    const float* Wv      = (const float*)d_in[6];
    const float* bv      = (const float*)d_in[7];
    const float* Wa      = (const float*)d_in[8];
    const float* ba      = (const float*)d_in[9];
    const float* rel_pri = (const float*)d_in[10];
    const float* rel_att = (const float*)d_in[11];
    const float* rel_msg = (const float*)d_in[12];
    const float* skip    = (const float*)d_in[13];
    const int* src_idx   = (const int*)d_in[14];
    const int* dst_idx   = (const int*)d_in[15];
    const int* etype     = (const int*)d_in[16];
    float* out = (float*)d_out;

    int n = in_sizes[0] / kD;
    int e = in_sizes[14];
    int nseg = n * kR;

    // one-time host-side setup (correctness call happens before graph capture)
    static bool inited = false;
    static cudaStream_t s1, s2, s3;
    static cudaEvent_t evRoot, ev1, ev2, ev3;
    if (!inited) {
        cudaStreamCreateWithFlags(&s1, cudaStreamNonBlocking);
        cudaStreamCreateWithFlags(&s2, cudaStreamNonBlocking);
        cudaStreamCreateWithFlags(&s3, cudaStreamNonBlocking);
        cudaEventCreateWithFlags(&evRoot, cudaEventDisableTiming);
        cudaEventCreateWithFlags(&ev1, cudaEventDisableTiming);
        cudaEventCreateWithFlags(&ev2, cudaEventDisableTiming);
        cudaEventCreateWithFlags(&ev3, cudaEventDisableTiming);
        cudaFuncSetAttribute(gemm_tf32, cudaFuncAttributeMaxDynamicSharedMemorySize,
                             GEMM_SMEM);
        inited = true;
    }

    float* pool = nullptr;
    cudaGetSymbolAddress((void**)&pool, g_pool);
    float* pq      = pool + OFF_Q;
    __half2* pkh   = (__half2*)(pool + OFF_KH);
    __half2* pvh   = (__half2*)(pool + OFF_VH);
    float* pt      = pool + OFF_T;
    __half2* pqrel = (__half2*)(pool + OFF_QRELH);
    __half* pmsp   = (__half*)(pool + OFF_MSP);
    unsigned* pcnt  = (unsigned*)(pool + OFF_CNT);
    unsigned* pcur  = (unsigned*)(pool + OFF_CUR);
    unsigned* pbsum = (unsigned*)(pool + OFF_BSUM);
    int* pssrc      = (int*)(pool + OFF_SSRC);
    uint2* pWq = (uint2*)(pool + OFF_WP);
    uint2* pWk = pWq + 8192;
    uint2* pWv = pWq + 16384;
    uint2* pWa = pWq + 24576;

    int gemm_blocks = (n + 127) / 128;
    int nb = (nseg + 1023) / 1024;

    // fork side streams from the capture (legacy default) stream
    cudaEventRecord(evRoot, 0);
    cudaStreamWaitEvent(s1, evRoot, 0);
    cudaStreamWaitEvent(s2, evRoot, 0);
    cudaStreamWaitEvent(s3, evRoot, 0);

    // s1: counting sort + rel_msg pack (independent of GEMMs)
    zero_cnt<<<(nseg + 256) / 256, 256, 0, s1>>>(pcnt, nseg);
    hist_kernel<<<(e + 255) / 256, 256, 0, s1>>>(dst_idx, etype, pcnt, e);
    scan_local<<<nb, 1024, 0, s1>>>(pcnt, pcnt, pbsum, nseg);
    scan_block<<<1, 1024, 0, s1>>>(pbsum, nb);
    scan_add<<<nb, 1024, 0, s1>>>(pcnt, pcur, pbsum, nseg, e);
    permute_kernel<<<(e + 255) / 256, 256, 0, s1>>>(src_idx, dst_idx, etype, pcur, pssrc, e);
    pack_msg<<<kR, 256, 0, s1>>>(rel_msg, pmsp);
    cudaEventRecord(ev1, s1);

    // s2: K projection
    pack_w<<<32, 256, 0, s2>>>(Wk, pWk);
    gemm_tf32<<<gemm_blocks, 256, GEMM_SMEM, s2>>>(src_h, pWk, bk, nullptr, nullptr,
                                                   nullptr, pkh, n, 0);
    cudaEventRecord(ev2, s2);

    // s3: V projection + Wa pack
    pack_w<<<32, 256, 0, s3>>>(Wv, pWv);
    gemm_tf32<<<gemm_blocks, 256, GEMM_SMEM, s3>>>(src_h, pWv, bv, nullptr, nullptr,
                                                   nullptr, pvh, n, 0);
    pack_w<<<32, 256, 0, s3>>>(Wa, pWa);
    cudaEventRecord(ev3, s3);

    // main stream: Q projection + qrel
    pack_w<<<32, 256>>>(Wq, pWq);
    gemm_tf32<<<gemm_blocks, 256, GEMM_SMEM>>>(dst_h, pWq, bq, nullptr, nullptr,
                                               pq, nullptr, n, 0);
    qrel_transform<<<(n + RT_TILE - 1) / RT_TILE, 256>>>(pq, rel_att, pqrel, n);

    // join all branches back into the capture stream
    cudaStreamWaitEvent(0, ev1, 0);
    cudaStreamWaitEvent(0, ev2, 0);
    cudaStreamWaitEvent(0, ev3, 0);

    // fused edge pass
    fused_edge2<<<((size_t)n * 32 + 511) / 512, 512>>>(pcnt, pssrc, pkh, pvh,
                                                       pqrel, pmsp, rel_pri, pt, n);

    // output projection + skip
    gemm_tf32<<<gemm_blocks, 256, GEMM_SMEM>>>(pt, pWa, ba, dst_h, skip, out,
                                               nullptr, n, 1);
}